// round 15
// baseline (speedup 1.0000x reference)
#include <cuda_runtime.h>
#include <cuda_fp16.h>
#include <math.h>
#include <stdint.h>

typedef __half  f16;
typedef __half2 f162;

// ---------------------------------------------------------------------------
// Problem constants
// ---------------------------------------------------------------------------
#define E_DIM   1024
#define H_NUM   16
#define HD_DIM  64
#define F_DIM   4096
#define B_NUM   4
#define S_LEN   2048
#define N_TOK   (B_NUM * S_LEN)      // 8192
#define BH_NUM  (B_NUM * H_NUM)      // 64
#define LN_EPS  1e-5f
#define QKV_LD  (3 * E_DIM)          // 3072

// ---------------------------------------------------------------------------
// Scratch buffers (static device globals)
// ---------------------------------------------------------------------------
__device__ float g_res1[(size_t)N_TOK * E_DIM];            // 32 MB
__device__ float g_h   [(size_t)N_TOK * E_DIM];
__device__ float g_res2[(size_t)N_TOK * E_DIM];
__device__ f16 g_xh   [(size_t)N_TOK * E_DIM];
__device__ f16 g_Wqkvh[(size_t)3 * E_DIM * E_DIM];         // concat [3072,1024]
__device__ f16 g_Woh  [(size_t)E_DIM * E_DIM];
__device__ f16 g_W1h  [(size_t)F_DIM * E_DIM];
__device__ f16 g_W2h  [(size_t)E_DIM * F_DIM];
__device__ f16 g_qkv  [(size_t)N_TOK * 3 * E_DIM];         // 48 MB [tok, 3072]
__device__ f16 g_ah   [(size_t)N_TOK * E_DIM];
__device__ f16 g_hh   [(size_t)N_TOK * E_DIM];
__device__ f16 g_fh   [(size_t)N_TOK * F_DIM];

// ---------------------------------------------------------------------------
// Helpers
// ---------------------------------------------------------------------------
__device__ __forceinline__ uint32_t smem_u32(const void* p) {
    return (uint32_t)__cvta_generic_to_shared(p);
}

__device__ __forceinline__ void ldsm4(uint32_t* r, uint32_t a) {
    asm volatile("ldmatrix.sync.aligned.m8n8.x4.shared.b16 {%0,%1,%2,%3}, [%4];"
        : "=r"(r[0]), "=r"(r[1]), "=r"(r[2]), "=r"(r[3]) : "r"(a));
}

__device__ __forceinline__ void ldsm4t(uint32_t* r, uint32_t a) {
    asm volatile("ldmatrix.sync.aligned.m8n8.x4.trans.shared.b16 {%0,%1,%2,%3}, [%4];"
        : "=r"(r[0]), "=r"(r[1]), "=r"(r[2]), "=r"(r[3]) : "r"(a));
}

// NOTE: non-volatile — pure register op, ordering enforced by data deps.
// Lets ptxas interleave MMAs with the next k-step's ldsm.
__device__ __forceinline__ void mma16816(float* c, const uint32_t* a, const uint32_t* b) {
    asm("mma.sync.aligned.m16n8k16.row.col.f32.f16.f16.f32 "
        "{%0,%1,%2,%3}, {%4,%5,%6,%7}, {%8,%9}, {%0,%1,%2,%3};"
        : "+f"(c[0]), "+f"(c[1]), "+f"(c[2]), "+f"(c[3])
        : "r"(a[0]), "r"(a[1]), "r"(a[2]), "r"(a[3]), "r"(b[0]), "r"(b[1]));
}

__device__ __forceinline__ void cpasync16(uint32_t dst, const void* src) {
    asm volatile("cp.async.cg.shared.global [%0], [%1], 16;\n" :: "r"(dst), "l"(src));
}
__device__ __forceinline__ void cpasync_commit() {
    asm volatile("cp.async.commit_group;\n");
}
template<int N>
__device__ __forceinline__ void cpasync_wait() {
    asm volatile("cp.async.wait_group %0;\n" :: "n"(N));
}

__device__ __forceinline__ float blockReduceSum256(float v) {
    __shared__ float s[8];
    int lane = threadIdx.x & 31, wid = threadIdx.x >> 5;
    #pragma unroll
    for (int o = 16; o; o >>= 1) v += __shfl_xor_sync(0xffffffffu, v, o);
    __syncthreads();
    if (lane == 0) s[wid] = v;
    __syncthreads();
    float r = s[0];
    #pragma unroll
    for (int i = 1; i < 8; i++) r += s[i];
    return r;
}

// ---------------------------------------------------------------------------
// fp16 tensor-core GEMM, BK=64, 3-stage cp.async pipeline + double-buffered
// register fragments (software pipeline: load kk+1 while issuing kk's MMAs).
// 1 CTA/SM (255-reg budget) so ptxas has headroom for the fragment pipeline.
// ---------------------------------------------------------------------------
#define GBK    64
#define GLDS   72            // 64 + 8 pad (halves)
#define GSTG   3

template<int BM, int BN, int WM, int WN>
__global__ __launch_bounds__(256) void gemm_fp16(
    const f16* __restrict__ A, int lda, long aOffB, long aOffH,
    const f16* __restrict__ B, int ldb, long bOffB, long bOffH,
    float* Cf32, f16* Ch,
    int ldc, long cOffB, long cOffH,
    const float* __restrict__ residual, const float* __restrict__ bias,
    int K, int nH, float alpha, int relu)
{
    constexpr int WARPS_N = BN / WN;
    constexpr int MF  = WM / 16;
    constexpr int NF  = WN / 8;
    constexpr int NG  = WN / 16;
    constexpr int AIT = (BM * GBK) / (8 * 256);
    constexpr int BIT = (BN * GBK) / (8 * 256);
    constexpr int A_STG = BM * GLDS;
    constexpr int B_STG = BN * GLDS;

    extern __shared__ __align__(16) f16 smemBuf[];
    f16* sA = smemBuf;
    f16* sB = sA + (size_t)GSTG * A_STG;

    const int tid  = threadIdx.x;
    const int warp = tid >> 5, lane = tid & 31;
    const int wr = warp / WARPS_N, wc = warp % WARPS_N;
    const int row0 = blockIdx.y * BM;
    const int col0 = blockIdx.x * BN;

    const int z  = blockIdx.z;
    const int zb = z / nH, zh = z % nH;
    const f16* Az = A + (long)zb * aOffB + (long)zh * aOffH;
    const f16* Bz = B + (long)zb * bOffB + (long)zh * bOffH;
    const long  zC = (long)zb * cOffB + (long)zh * cOffH;

    float acc[MF][NF][4];
    #pragma unroll
    for (int i = 0; i < MF; i++)
        #pragma unroll
        for (int j = 0; j < NF; j++)
            #pragma unroll
            for (int k = 0; k < 4; k++) acc[i][j][k] = 0.f;

    auto issueTile = [&](int kt) {
        const int stage = kt % GSTG;
        const int k0 = kt * GBK;
        #pragma unroll
        for (int i = 0; i < AIT; i++) {
            int idx = tid + i * 256, r = idx >> 3, c = (idx & 7) * 8;
            cpasync16(smem_u32(sA + (uint32_t)((stage * BM + r) * GLDS + c)),
                      Az + (long)(row0 + r) * lda + k0 + c);
        }
        #pragma unroll
        for (int i = 0; i < BIT; i++) {
            int idx = tid + i * 256, r = idx >> 3, c = (idx & 7) * 8;
            cpasync16(smem_u32(sB + (uint32_t)((stage * BN + r) * GLDS + c)),
                      Bz + (long)(col0 + r) * ldb + k0 + c);
        }
    };

    const int KT = K / GBK;

    #pragma unroll
    for (int s = 0; s < GSTG - 1; s++) {
        if (s < KT) issueTile(s);
        cpasync_commit();
    }

    const int aRowL = ((lane >> 3) & 1) * 8 + (lane & 7);
    const int aColL = (lane >> 4) * 8;
    const int bRowL = (lane >> 4) * 8 + (lane & 7);
    const int bColL = ((lane >> 3) & 1) * 8;
    const uint32_t aBase0 = smem_u32(sA) + ((wr * WM + aRowL) * GLDS + aColL) * 2;
    const uint32_t bBase0 = smem_u32(sB) + ((wc * WN + bRowL) * GLDS + bColL) * 2;

    for (int kt = 0; kt < KT; kt++) {
        if (kt == KT - 1) cpasync_wait<0>();
        else              cpasync_wait<GSTG - 2>();
        __syncthreads();

        int nk = kt + GSTG - 1;
        if (nk < KT) issueTile(nk);
        cpasync_commit();

        const int stage = kt % GSTG;
        const uint32_t aB = aBase0 + (uint32_t)(stage * A_STG * 2);
        const uint32_t bB = bBase0 + (uint32_t)(stage * B_STG * 2);

        // double-buffered fragments: load kk+1 while mma'ing kk
        uint32_t aR[2][MF][4];
        uint32_t bR[2][NG][4];
        #pragma unroll
        for (int mi = 0; mi < MF; mi++)
            ldsm4(aR[0][mi], aB + mi * (16 * GLDS * 2));
        #pragma unroll
        for (int gi = 0; gi < NG; gi++)
            ldsm4(bR[0][gi], bB + gi * (16 * GLDS * 2));

        #pragma unroll
        for (int kk = 0; kk < 4; kk++) {               // 4 x k16 per 64-tile
            const int cur = kk & 1, nxt = cur ^ 1;
            if (kk < 3) {
                const uint32_t koff = (kk + 1) * 32;
                #pragma unroll
                for (int mi = 0; mi < MF; mi++)
                    ldsm4(aR[nxt][mi], aB + mi * (16 * GLDS * 2) + koff);
                #pragma unroll
                for (int gi = 0; gi < NG; gi++)
                    ldsm4(bR[nxt][gi], bB + gi * (16 * GLDS * 2) + koff);
            }
            #pragma unroll
            for (int mi = 0; mi < MF; mi++)
                #pragma unroll
                for (int gi = 0; gi < NG; gi++) {
                    mma16816(acc[mi][2 * gi],     aR[cur][mi], &bR[cur][gi][0]);
                    mma16816(acc[mi][2 * gi + 1], aR[cur][mi], &bR[cur][gi][2]);
                }
        }
    }

    float*       Cz = Cf32 ? Cf32 + zC : nullptr;
    f16*         CH = Ch   ? Ch   + zC : nullptr;
    const float* Rz = residual ? residual + zC : nullptr;

    #pragma unroll
    for (int mi = 0; mi < MF; mi++)
        #pragma unroll
        for (int nf = 0; nf < NF; nf++) {
            int rbase = row0 + wr * WM + mi * 16 + (lane >> 2);
            int c     = col0 + wc * WN + nf * 8 + (lane & 3) * 2;
            #pragma unroll
            for (int half = 0; half < 2; half++) {
                long r = rbase + half * 8;
                float v0 = acc[mi][nf][half * 2 + 0] * alpha;
                float v1 = acc[mi][nf][half * 2 + 1] * alpha;
                if (bias) { v0 += bias[c]; v1 += bias[c + 1]; }
                if (relu) { v0 = fmaxf(v0, 0.f); v1 = fmaxf(v1, 0.f); }
                if (Rz)   { v0 += Rz[r * (long)ldc + c]; v1 += Rz[r * (long)ldc + c + 1]; }
                if (Cz) *(float2*)&Cz[r * (long)ldc + c] = make_float2(v0, v1);
                if (CH) *(f162*)&CH[r * (long)ldc + c] =
                            __floats2half2_rn(v0, v1);
            }
        }
}

// ---------------------------------------------------------------------------
// Flash attention (proven R13/R14): Q/K/V from fused qkv buffer, V via trans.
// ---------------------------------------------------------------------------
#define FT_QT  128
#define FT_KT  64
#define FLDS   72

__global__ __launch_bounds__(256) void flash_attn(
    const f16* __restrict__ QKVg, f16* __restrict__ Og)
{
    extern __shared__ __align__(16) f16 sm[];
    f16* sQ = sm;                              // [128][72]
    f16* sK = sQ + FT_QT * FLDS;               // [2][64][72]
    f16* sV = sK + 2 * FT_KT * FLDS;           // [2][64][72], rows = kv
    const int tid = threadIdx.x, warp = tid >> 5, lane = tid & 31;
    const int q0 = blockIdx.x * FT_QT;
    const int bh = blockIdx.y, b = bh >> 4, h = bh & 15;

    const f16* Qz = QKVg + ((size_t)b * S_LEN + q0) * QKV_LD + h * HD_DIM;
    const f16* Kz = QKVg + ((size_t)b * S_LEN) * QKV_LD + E_DIM + h * HD_DIM;
    const f16* Vz = QKVg + ((size_t)b * S_LEN) * QKV_LD + 2 * E_DIM + h * HD_DIM;
    f16* Oz = Og + ((size_t)b * S_LEN + q0) * E_DIM + h * HD_DIM;

    #pragma unroll
    for (int i = 0; i < 4; i++) {
        int idx = tid + i * 256, r = idx >> 3, g = idx & 7;
        cpasync16(smem_u32(sQ + r * FLDS + g * 8), Qz + (size_t)r * QKV_LD + g * 8);
    }
    auto loadKV = [&](int j) {
        const int buf = j & 1;
        const int kv0 = j * FT_KT;
        #pragma unroll
        for (int i = 0; i < 2; i++) {
            int idx = tid + i * 256, r = idx >> 3, g = idx & 7;
            cpasync16(smem_u32(sK + (buf * FT_KT + r) * FLDS + g * 8),
                      Kz + (size_t)(kv0 + r) * QKV_LD + g * 8);
            cpasync16(smem_u32(sV + (buf * FT_KT + r) * FLDS + g * 8),
                      Vz + (size_t)(kv0 + r) * QKV_LD + g * 8);
        }
    };
    loadKV(0);
    cpasync_commit();

    const int aRowL = ((lane >> 3) & 1) * 8 + (lane & 7);
    const int aColL = (lane >> 4) * 8;
    const int bRowL = (lane >> 4) * 8 + (lane & 7);
    const int bColL = ((lane >> 3) & 1) * 8;
    const uint32_t qBase = smem_u32(sQ) + ((warp * 16 + aRowL) * FLDS + aColL) * 2;
    const uint32_t kBase = smem_u32(sK) + (bRowL * FLDS + bColL) * 2;
    const uint32_t vBase = smem_u32(sV) + (aRowL * FLDS + aColL) * 2;
    const uint32_t bufB = FT_KT * FLDS * 2;

    float o[8][4];
    #pragma unroll
    for (int d = 0; d < 8; d++)
        #pragma unroll
        for (int c = 0; c < 4; c++) o[d][c] = 0.f;
    float mrow[2] = { -1e30f, -1e30f };
    float lrow[2] = { 0.f, 0.f };
    uint32_t aQ[4][4];

    const int NT = S_LEN / FT_KT;   // 32
    for (int j = 0; j < NT; j++) {
        if (j + 1 < NT) { loadKV(j + 1); cpasync_commit(); cpasync_wait<1>(); }
        else            { cpasync_commit(); cpasync_wait<0>(); }
        __syncthreads();

        if (j == 0) {
            #pragma unroll
            for (int ks = 0; ks < 4; ks++) ldsm4(aQ[ks], qBase + ks * 32);
        }

        const uint32_t kB = kBase + (uint32_t)(j & 1) * bufB;
        const uint32_t vB = vBase + (uint32_t)(j & 1) * bufB;

        float s[8][4];
        #pragma unroll
        for (int nf = 0; nf < 8; nf++)
            #pragma unroll
            for (int c = 0; c < 4; c++) s[nf][c] = 0.f;
        #pragma unroll
        for (int ks = 0; ks < 4; ks++) {
            #pragma unroll
            for (int gi = 0; gi < 4; gi++) {
                uint32_t t4[4];
                ldsm4(t4, kB + gi * (16 * FLDS * 2) + ks * 32);
                mma16816(s[2 * gi],     aQ[ks], t4);
                mma16816(s[2 * gi + 1], aQ[ks], t4 + 2);
            }
        }
        #pragma unroll
        for (int nf = 0; nf < 8; nf++)
            #pragma unroll
            for (int c = 0; c < 4; c++) s[nf][c] *= 0.125f;

        #pragma unroll
        for (int hf = 0; hf < 2; hf++) {
            float mx = -1e30f;
            #pragma unroll
            for (int nf = 0; nf < 8; nf++)
                mx = fmaxf(mx, fmaxf(s[nf][2 * hf], s[nf][2 * hf + 1]));
            mx = fmaxf(mx, __shfl_xor_sync(0xffffffffu, mx, 1));
            mx = fmaxf(mx, __shfl_xor_sync(0xffffffffu, mx, 2));
            float mnew = fmaxf(mrow[hf], mx);
            float alpha = __expf(mrow[hf] - mnew);
            mrow[hf] = mnew;
            float rs = 0.f;
            #pragma unroll
            for (int nf = 0; nf < 8; nf++) {
                float p0 = __expf(s[nf][2 * hf]     - mnew);
                float p1 = __expf(s[nf][2 * hf + 1] - mnew);
                s[nf][2 * hf] = p0; s[nf][2 * hf + 1] = p1;
                rs += p0 + p1;
            }
            rs += __shfl_xor_sync(0xffffffffu, rs, 1);
            rs += __shfl_xor_sync(0xffffffffu, rs, 2);
            lrow[hf] = lrow[hf] * alpha + rs;
            #pragma unroll
            for (int df = 0; df < 8; df++) {
                o[df][2 * hf]     *= alpha;
                o[df][2 * hf + 1] *= alpha;
            }
        }

        uint32_t aP[4][4];
        #pragma unroll
        for (int ks = 0; ks < 4; ks++) {
            f162 h0 = __floats2half2_rn(s[2 * ks][0],     s[2 * ks][1]);
            f162 h1 = __floats2half2_rn(s[2 * ks][2],     s[2 * ks][3]);
            f162 h2 = __floats2half2_rn(s[2 * ks + 1][0], s[2 * ks + 1][1]);
            f162 h3 = __floats2half2_rn(s[2 * ks + 1][2], s[2 * ks + 1][3]);
            aP[ks][0] = *(uint32_t*)&h0; aP[ks][1] = *(uint32_t*)&h1;
            aP[ks][2] = *(uint32_t*)&h2; aP[ks][3] = *(uint32_t*)&h3;
        }

        #pragma unroll
        for (int ks = 0; ks < 4; ks++) {
            #pragma unroll
            for (int gi = 0; gi < 4; gi++) {
                uint32_t t4[4];
                ldsm4t(t4, vB + (ks * 16 * FLDS + gi * 16) * 2);
                mma16816(o[2 * gi],     aP[ks], t4);
                mma16816(o[2 * gi + 1], aP[ks], t4 + 2);
            }
        }
        __syncthreads();
    }

    #pragma unroll
    for (int hf = 0; hf < 2; hf++) {
        float inv = 1.f / lrow[hf];
        size_t r = (size_t)(warp * 16 + (lane >> 2) + hf * 8);
        #pragma unroll
        for (int df = 0; df < 8; df++) {
            int c = df * 8 + (lane & 3) * 2;
            *(f162*)&Oz[r * E_DIM + c] =
                __floats2half2_rn(o[df][2 * hf] * inv, o[df][2 * hf + 1] * inv);
        }
    }
}

// ---------------------------------------------------------------------------
// Fused fp32->fp16 conversion: 7 segments in one launch (grid.y = segment).
// ---------------------------------------------------------------------------
struct CvtSeg { const float* src; f16* dst; size_t n4; };

__global__ void cvt_all(CvtSeg s0, CvtSeg s1, CvtSeg s2, CvtSeg s3,
                        CvtSeg s4, CvtSeg s5, CvtSeg s6)
{
    CvtSeg seg;
    switch (blockIdx.y) {
        case 0: seg = s0; break;
        case 1: seg = s1; break;
        case 2: seg = s2; break;
        case 3: seg = s3; break;
        case 4: seg = s4; break;
        case 5: seg = s5; break;
        default: seg = s6; break;
    }
    size_t i = (size_t)blockIdx.x * blockDim.x + threadIdx.x;
    if (i >= seg.n4) return;
    float4 v = ((const float4*)seg.src)[i];
    ((f162*)seg.dst)[2 * i + 0] = __floats2half2_rn(v.x, v.y);
    ((f162*)seg.dst)[2 * i + 1] = __floats2half2_rn(v.z, v.w);
}

// ---------------------------------------------------------------------------
// LayerNorm (E=1024), fp32 out + optional fp16 out
// ---------------------------------------------------------------------------
__global__ __launch_bounds__(256) void layernorm_rows(
    const float* __restrict__ in,
    const float* __restrict__ g, const float* __restrict__ b,
    float* __restrict__ out, f16* __restrict__ oh)
{
    size_t row = blockIdx.x;
    const float4* x4 = (const float4*)(in + row * E_DIM);
    float4 v = x4[threadIdx.x];

    float s  = v.x + v.y + v.z + v.w;
    float ss = v.x * v.x + v.y * v.y + v.z * v.z + v.w * v.w;
    s  = blockReduceSum256(s);
    ss = blockReduceSum256(ss);

    const float invE = 1.f / (float)E_DIM;
    float mu   = s * invE;
    float var  = ss * invE - mu * mu;
    float rstd = rsqrtf(var + LN_EPS);

    float4 gv = ((const float4*)g)[threadIdx.x];
    float4 bv = ((const float4*)b)[threadIdx.x];
    float4 o;
    o.x = (v.x - mu) * rstd * gv.x + bv.x;
    o.y = (v.y - mu) * rstd * gv.y + bv.y;
    o.z = (v.z - mu) * rstd * gv.z + bv.z;
    o.w = (v.w - mu) * rstd * gv.w + bv.w;
    ((float4*)(out + row * E_DIM))[threadIdx.x] = o;

    if (oh) {
        f162* ph = (f162*)(oh + row * E_DIM);
        ph[2 * threadIdx.x + 0] = __floats2half2_rn(o.x, o.y);
        ph[2 * threadIdx.x + 1] = __floats2half2_rn(o.z, o.w);
    }
}

// ---------------------------------------------------------------------------
// Launch
// Inputs: 0:x 1:Wq 2:Wk 3:Wv 4:Wo 5:g1 6:b1 7:g2 8:b2 9:W1 10:bb1 11:W2 12:bb2
// ---------------------------------------------------------------------------
#define SYMADDR(v, s) cudaGetSymbolAddress((void**)&v, s)
#define GEMM_SMEM(BM, BN) (GSTG * ((BM) + (BN)) * GLDS * 2)
#define FLASH_SMEM ((FT_QT + 4 * FT_KT) * FLDS * 2)   // 55296 B

extern "C" void kernel_launch(void* const* d_in, const int* in_sizes, int n_in,
                              void* d_out, int out_size)
{
    const float* x   = (const float*)d_in[0];
    const float* Wq  = (const float*)d_in[1];
    const float* Wk  = (const float*)d_in[2];
    const float* Wv  = (const float*)d_in[3];
    const float* Wo  = (const float*)d_in[4];
    const float* g1  = (const float*)d_in[5];
    const float* b1  = (const float*)d_in[6];
    const float* g2  = (const float*)d_in[7];
    const float* b2  = (const float*)d_in[8];
    const float* W1  = (const float*)d_in[9];
    const float* bb1 = (const float*)d_in[10];
    const float* W2  = (const float*)d_in[11];
    const float* bb2 = (const float*)d_in[12];
    float* out = (float*)d_out;

    float *res1, *h, *res2;
    f16 *xh, *Wqkvh, *Woh, *W1h, *W2h;
    f16 *qkv, *ah, *hh, *fh;
    SYMADDR(res1, g_res1);
    SYMADDR(h, g_h); SYMADDR(res2, g_res2);
    SYMADDR(xh, g_xh);
    SYMADDR(Wqkvh, g_Wqkvh); SYMADDR(Woh, g_Woh);
    SYMADDR(W1h, g_W1h); SYMADDR(W2h, g_W2h);
    SYMADDR(qkv, g_qkv);
    SYMADDR(ah, g_ah); SYMADDR(hh, g_hh); SYMADDR(fh, g_fh);

    const int SM_128 = GEMM_SMEM(128, 128);   // 110592
    cudaFuncSetAttribute(gemm_fp16<128,128,64,32>,
                         cudaFuncAttributeMaxDynamicSharedMemorySize, SM_128);
    cudaFuncSetAttribute(flash_attn,
                         cudaFuncAttributeMaxDynamicSharedMemorySize, FLASH_SMEM);

    dim3 blk(256);

    // --- single fused convert launch ---
    const size_t nE2 = (size_t)E_DIM * E_DIM;
    CvtSeg s0 = { x,  xh,  (size_t)N_TOK * E_DIM / 4 };
    CvtSeg s1 = { Wq, Wqkvh,            nE2 / 4 };
    CvtSeg s2 = { Wk, Wqkvh + nE2,      nE2 / 4 };
    CvtSeg s3 = { Wv, Wqkvh + 2 * nE2,  nE2 / 4 };
    CvtSeg s4 = { Wo, Woh,              nE2 / 4 };
    CvtSeg s5 = { W1, W1h, (size_t)F_DIM * E_DIM / 4 };
    CvtSeg s6 = { W2, W2h, (size_t)E_DIM * F_DIM / 4 };
    size_t maxN4 = (size_t)N_TOK * E_DIM / 4;
    dim3 gcvt((unsigned)((maxN4 + 255) / 256), 7);
    cvt_all<<<gcvt, blk>>>(s0, s1, s2, s3, s4, s5, s6);

    // --- fused QKV projection -> qkv fp16 [tok, 3072] ---
    dim3 gqkv(QKV_LD / 128, N_TOK / 128, 1);
    gemm_fp16<128,128,64,32><<<gqkv, blk, SM_128>>>(
        xh, E_DIM, 0, 0,  Wqkvh, E_DIM, 0, 0,
        nullptr, qkv, QKV_LD, 0, 0,
        nullptr, nullptr, E_DIM, 1, 1.f, 0);

    // --- fused flash attention -> ah fp16 ---
    flash_attn<<<dim3(S_LEN / FT_QT, BH_NUM), blk, FLASH_SMEM>>>(qkv, ah);

    // --- O projection + residual x ---
    dim3 gp(E_DIM / 128, N_TOK / 128, 1);
    gemm_fp16<128,128,64,32><<<gp, blk, SM_128>>>(
        ah, E_DIM, 0, 0,  Woh, E_DIM, 0, 0,
        res1, nullptr, E_DIM, 0, 0,
        x, nullptr, E_DIM, 1, 1.f, 0);

    // --- LN1 -> h (fp32 + fp16) ---
    layernorm_rows<<<N_TOK, 256>>>(res1, g1, b1, h, hh);

    // --- FFN1: relu(h @ W1^T + bb1) -> fp16 ---
    dim3 gf1(F_DIM / 128, N_TOK / 128, 1);
    gemm_fp16<128,128,64,32><<<gf1, blk, SM_128>>>(
        hh, E_DIM, 0, 0,  W1h, E_DIM, 0, 0,
        nullptr, fh, F_DIM, 0, 0,
        nullptr, bb1, E_DIM, 1, 1.f, 1);

    // --- FFN2: ffn @ W2^T + bb2 + h ---
    gemm_fp16<128,128,64,32><<<gp, blk, SM_128>>>(
        fh, F_DIM, 0, 0,  W2h, F_DIM, 0, 0,
        res2, nullptr, E_DIM, 0, 0,
        h, bb2, F_DIM, 1, 1.f, 0);

    // --- LN2 -> out ---
    layernorm_rows<<<N_TOK, 256>>>(res2, g2, b2, out, nullptr);
}

// round 17
// speedup vs baseline: 1.0540x; 1.0540x over previous
#include <cuda_runtime.h>
#include <cuda_fp16.h>
#include <math.h>
#include <stdint.h>

typedef __half  f16;
typedef __half2 f162;

// ---------------------------------------------------------------------------
// Problem constants
// ---------------------------------------------------------------------------
#define E_DIM   1024
#define H_NUM   16
#define HD_DIM  64
#define F_DIM   4096
#define B_NUM   4
#define S_LEN   2048
#define N_TOK   (B_NUM * S_LEN)      // 8192
#define BH_NUM  (B_NUM * H_NUM)      // 64
#define LN_EPS  1e-5f
#define QKV_LD  (3 * E_DIM)          // 3072

// ---------------------------------------------------------------------------
// Scratch buffers (static device globals)
// ---------------------------------------------------------------------------
__device__ float g_res1[(size_t)N_TOK * E_DIM];            // 32 MB
__device__ float g_h   [(size_t)N_TOK * E_DIM];
__device__ float g_res2[(size_t)N_TOK * E_DIM];
__device__ f16 g_xh   [(size_t)N_TOK * E_DIM];
__device__ f16 g_Wqkvh[(size_t)3 * E_DIM * E_DIM];         // concat [3072,1024]
__device__ f16 g_Woh  [(size_t)E_DIM * E_DIM];
__device__ f16 g_W1h  [(size_t)F_DIM * E_DIM];
__device__ f16 g_W2h  [(size_t)E_DIM * F_DIM];
__device__ f16 g_qkv  [(size_t)N_TOK * 3 * E_DIM];         // 48 MB [tok, 3072]
__device__ f16 g_ah   [(size_t)N_TOK * E_DIM];
__device__ f16 g_hh   [(size_t)N_TOK * E_DIM];
__device__ f16 g_fh   [(size_t)N_TOK * F_DIM];

// ---------------------------------------------------------------------------
// Helpers
// ---------------------------------------------------------------------------
__device__ __forceinline__ uint32_t smem_u32(const void* p) {
    return (uint32_t)__cvta_generic_to_shared(p);
}

__device__ __forceinline__ void ldsm4(uint32_t* r, uint32_t a) {
    asm volatile("ldmatrix.sync.aligned.m8n8.x4.shared.b16 {%0,%1,%2,%3}, [%4];"
        : "=r"(r[0]), "=r"(r[1]), "=r"(r[2]), "=r"(r[3]) : "r"(a));
}

__device__ __forceinline__ void ldsm4t(uint32_t* r, uint32_t a) {
    asm volatile("ldmatrix.sync.aligned.m8n8.x4.trans.shared.b16 {%0,%1,%2,%3}, [%4];"
        : "=r"(r[0]), "=r"(r[1]), "=r"(r[2]), "=r"(r[3]) : "r"(a));
}

__device__ __forceinline__ void mma16816(float* c, const uint32_t* a, const uint32_t* b) {
    asm volatile(
        "mma.sync.aligned.m16n8k16.row.col.f32.f16.f16.f32 "
        "{%0,%1,%2,%3}, {%4,%5,%6,%7}, {%8,%9}, {%0,%1,%2,%3};"
        : "+f"(c[0]), "+f"(c[1]), "+f"(c[2]), "+f"(c[3])
        : "r"(a[0]), "r"(a[1]), "r"(a[2]), "r"(a[3]), "r"(b[0]), "r"(b[1]));
}

__device__ __forceinline__ void cpasync16(uint32_t dst, const void* src) {
    asm volatile("cp.async.cg.shared.global [%0], [%1], 16;\n" :: "r"(dst), "l"(src));
}
__device__ __forceinline__ void cpasync_commit() {
    asm volatile("cp.async.commit_group;\n");
}
template<int N>
__device__ __forceinline__ void cpasync_wait() {
    asm volatile("cp.async.wait_group %0;\n" :: "n"(N));
}

__device__ __forceinline__ float blockReduceSum256(float v) {
    __shared__ float s[8];
    int lane = threadIdx.x & 31, wid = threadIdx.x >> 5;
    #pragma unroll
    for (int o = 16; o; o >>= 1) v += __shfl_xor_sync(0xffffffffu, v, o);
    __syncthreads();
    if (lane == 0) s[wid] = v;
    __syncthreads();
    float r = s[0];
    #pragma unroll
    for (int i = 1; i < 8; i++) r += s[i];
    return r;
}

// ---------------------------------------------------------------------------
// fp16 tensor-core GEMM, BK=64, 3-stage cp.async pipeline (R14 winner,
// reverted verbatim: tensor% is ceiling-bound; interior tuning exhausted).
// ---------------------------------------------------------------------------
#define GBK    64
#define GLDS   72            // 64 + 8 pad (halves)
#define GSTG   3

template<int BM, int BN, int WM, int WN>
__global__ __launch_bounds__(256, 2) void gemm_fp16(
    const f16* __restrict__ A, int lda, long aOffB, long aOffH,
    const f16* __restrict__ B, int ldb, long bOffB, long bOffH,
    float* Cf32, f16* Ch,
    int ldc, long cOffB, long cOffH,
    const float* __restrict__ residual, const float* __restrict__ bias,
    int K, int nH, float alpha, int relu)
{
    constexpr int WARPS_N = BN / WN;
    constexpr int MF  = WM / 16;
    constexpr int NF  = WN / 8;
    constexpr int NG  = WN / 16;
    constexpr int AIT = (BM * GBK) / (8 * 256);
    constexpr int BIT = (BN * GBK) / (8 * 256);
    constexpr int A_STG = BM * GLDS;
    constexpr int B_STG = BN * GLDS;

    extern __shared__ __align__(16) f16 smemBuf[];
    f16* sA = smemBuf;
    f16* sB = sA + (size_t)GSTG * A_STG;

    const int tid  = threadIdx.x;
    const int warp = tid >> 5, lane = tid & 31;
    const int wr = warp / WARPS_N, wc = warp % WARPS_N;
    const int row0 = blockIdx.y * BM;
    const int col0 = blockIdx.x * BN;

    const int z  = blockIdx.z;
    const int zb = z / nH, zh = z % nH;
    const f16* Az = A + (long)zb * aOffB + (long)zh * aOffH;
    const f16* Bz = B + (long)zb * bOffB + (long)zh * bOffH;
    const long  zC = (long)zb * cOffB + (long)zh * cOffH;

    float acc[MF][NF][4];
    #pragma unroll
    for (int i = 0; i < MF; i++)
        #pragma unroll
        for (int j = 0; j < NF; j++)
            #pragma unroll
            for (int k = 0; k < 4; k++) acc[i][j][k] = 0.f;

    auto issueTile = [&](int kt) {
        const int stage = kt % GSTG;
        const int k0 = kt * GBK;
        #pragma unroll
        for (int i = 0; i < AIT; i++) {
            int idx = tid + i * 256, r = idx >> 3, c = (idx & 7) * 8;
            cpasync16(smem_u32(sA + (uint32_t)((stage * BM + r) * GLDS + c)),
                      Az + (long)(row0 + r) * lda + k0 + c);
        }
        #pragma unroll
        for (int i = 0; i < BIT; i++) {
            int idx = tid + i * 256, r = idx >> 3, c = (idx & 7) * 8;
            cpasync16(smem_u32(sB + (uint32_t)((stage * BN + r) * GLDS + c)),
                      Bz + (long)(col0 + r) * ldb + k0 + c);
        }
    };

    const int KT = K / GBK;

    #pragma unroll
    for (int s = 0; s < GSTG - 1; s++) {
        if (s < KT) issueTile(s);
        cpasync_commit();
    }

    const int aRowL = ((lane >> 3) & 1) * 8 + (lane & 7);
    const int aColL = (lane >> 4) * 8;
    const int bRowL = (lane >> 4) * 8 + (lane & 7);
    const int bColL = ((lane >> 3) & 1) * 8;
    const uint32_t aBase0 = smem_u32(sA) + ((wr * WM + aRowL) * GLDS + aColL) * 2;
    const uint32_t bBase0 = smem_u32(sB) + ((wc * WN + bRowL) * GLDS + bColL) * 2;

    for (int kt = 0; kt < KT; kt++) {
        if (kt == KT - 1) cpasync_wait<0>();
        else              cpasync_wait<GSTG - 2>();
        __syncthreads();

        int nk = kt + GSTG - 1;
        if (nk < KT) issueTile(nk);
        cpasync_commit();

        const int stage = kt % GSTG;
        const uint32_t sOffA = (uint32_t)(stage * A_STG * 2);
        const uint32_t sOffB = (uint32_t)(stage * B_STG * 2);

        #pragma unroll
        for (int kk = 0; kk < 4; kk++) {               // 4 x k16 per tile
            const uint32_t koff = kk * 32;             // 16 elems * 2B
            uint32_t aR[MF][4];
            #pragma unroll
            for (int mi = 0; mi < MF; mi++)
                ldsm4(aR[mi], aBase0 + sOffA + mi * (16 * GLDS * 2) + koff);
            uint32_t bR[NF][2];
            #pragma unroll
            for (int gi = 0; gi < NG; gi++) {
                uint32_t t4[4];
                ldsm4(t4, bBase0 + sOffB + gi * (16 * GLDS * 2) + koff);
                bR[2 * gi][0] = t4[0]; bR[2 * gi][1] = t4[1];
                bR[2 * gi + 1][0] = t4[2]; bR[2 * gi + 1][1] = t4[3];
            }
            #pragma unroll
            for (int mi = 0; mi < MF; mi++)
                #pragma unroll
                for (int nf = 0; nf < NF; nf++)
                    mma16816(acc[mi][nf], aR[mi], bR[nf]);
        }
    }

    float*       Cz = Cf32 ? Cf32 + zC : nullptr;
    f16*         CH = Ch   ? Ch   + zC : nullptr;
    const float* Rz = residual ? residual + zC : nullptr;

    #pragma unroll
    for (int mi = 0; mi < MF; mi++)
        #pragma unroll
        for (int nf = 0; nf < NF; nf++) {
            int rbase = row0 + wr * WM + mi * 16 + (lane >> 2);
            int c     = col0 + wc * WN + nf * 8 + (lane & 3) * 2;
            #pragma unroll
            for (int half = 0; half < 2; half++) {
                long r = rbase + half * 8;
                float v0 = acc[mi][nf][half * 2 + 0] * alpha;
                float v1 = acc[mi][nf][half * 2 + 1] * alpha;
                if (bias) { v0 += bias[c]; v1 += bias[c + 1]; }
                if (relu) { v0 = fmaxf(v0, 0.f); v1 = fmaxf(v1, 0.f); }
                if (Rz)   { v0 += Rz[r * (long)ldc + c]; v1 += Rz[r * (long)ldc + c + 1]; }
                if (Cz) *(float2*)&Cz[r * (long)ldc + c] = make_float2(v0, v1);
                if (CH) *(f162*)&CH[r * (long)ldc + c] =
                            __floats2half2_rn(v0, v1);
            }
        }
}

// ---------------------------------------------------------------------------
// Flash attention (proven R13/R14) — 2 CTAs/SM: smem 55.3 KB x2 fits,
// reg budget 128 forces co-residency so a second CTA overlaps softmax phases.
// ---------------------------------------------------------------------------
#define FT_QT  128
#define FT_KT  64
#define FLDS   72

__global__ __launch_bounds__(256, 2) void flash_attn(
    const f16* __restrict__ QKVg, f16* __restrict__ Og)
{
    extern __shared__ __align__(16) f16 sm[];
    f16* sQ = sm;                              // [128][72]
    f16* sK = sQ + FT_QT * FLDS;               // [2][64][72]
    f16* sV = sK + 2 * FT_KT * FLDS;           // [2][64][72], rows = kv
    const int tid = threadIdx.x, warp = tid >> 5, lane = tid & 31;
    const int q0 = blockIdx.x * FT_QT;
    const int bh = blockIdx.y, b = bh >> 4, h = bh & 15;

    const f16* Qz = QKVg + ((size_t)b * S_LEN + q0) * QKV_LD + h * HD_DIM;
    const f16* Kz = QKVg + ((size_t)b * S_LEN) * QKV_LD + E_DIM + h * HD_DIM;
    const f16* Vz = QKVg + ((size_t)b * S_LEN) * QKV_LD + 2 * E_DIM + h * HD_DIM;
    f16* Oz = Og + ((size_t)b * S_LEN + q0) * E_DIM + h * HD_DIM;

    #pragma unroll
    for (int i = 0; i < 4; i++) {
        int idx = tid + i * 256, r = idx >> 3, g = idx & 7;
        cpasync16(smem_u32(sQ + r * FLDS + g * 8), Qz + (size_t)r * QKV_LD + g * 8);
    }
    auto loadKV = [&](int j) {
        const int buf = j & 1;
        const int kv0 = j * FT_KT;
        #pragma unroll
        for (int i = 0; i < 2; i++) {
            int idx = tid + i * 256, r = idx >> 3, g = idx & 7;
            cpasync16(smem_u32(sK + (buf * FT_KT + r) * FLDS + g * 8),
                      Kz + (size_t)(kv0 + r) * QKV_LD + g * 8);
            cpasync16(smem_u32(sV + (buf * FT_KT + r) * FLDS + g * 8),
                      Vz + (size_t)(kv0 + r) * QKV_LD + g * 8);
        }
    };
    loadKV(0);
    cpasync_commit();

    const int aRowL = ((lane >> 3) & 1) * 8 + (lane & 7);
    const int aColL = (lane >> 4) * 8;
    const int bRowL = (lane >> 4) * 8 + (lane & 7);
    const int bColL = ((lane >> 3) & 1) * 8;
    const uint32_t qBase = smem_u32(sQ) + ((warp * 16 + aRowL) * FLDS + aColL) * 2;
    const uint32_t kBase = smem_u32(sK) + (bRowL * FLDS + bColL) * 2;
    const uint32_t vBase = smem_u32(sV) + (aRowL * FLDS + aColL) * 2;
    const uint32_t bufB = FT_KT * FLDS * 2;

    float o[8][4];
    #pragma unroll
    for (int d = 0; d < 8; d++)
        #pragma unroll
        for (int c = 0; c < 4; c++) o[d][c] = 0.f;
    float mrow[2] = { -1e30f, -1e30f };
    float lrow[2] = { 0.f, 0.f };
    uint32_t aQ[4][4];

    const int NT = S_LEN / FT_KT;   // 32
    for (int j = 0; j < NT; j++) {
        if (j + 1 < NT) { loadKV(j + 1); cpasync_commit(); cpasync_wait<1>(); }
        else            { cpasync_commit(); cpasync_wait<0>(); }
        __syncthreads();

        if (j == 0) {
            #pragma unroll
            for (int ks = 0; ks < 4; ks++) ldsm4(aQ[ks], qBase + ks * 32);
        }

        const uint32_t kB = kBase + (uint32_t)(j & 1) * bufB;
        const uint32_t vB = vBase + (uint32_t)(j & 1) * bufB;

        float s[8][4];
        #pragma unroll
        for (int nf = 0; nf < 8; nf++)
            #pragma unroll
            for (int c = 0; c < 4; c++) s[nf][c] = 0.f;
        #pragma unroll
        for (int ks = 0; ks < 4; ks++) {
            #pragma unroll
            for (int gi = 0; gi < 4; gi++) {
                uint32_t t4[4];
                ldsm4(t4, kB + gi * (16 * FLDS * 2) + ks * 32);
                mma16816(s[2 * gi],     aQ[ks], t4);
                mma16816(s[2 * gi + 1], aQ[ks], t4 + 2);
            }
        }
        #pragma unroll
        for (int nf = 0; nf < 8; nf++)
            #pragma unroll
            for (int c = 0; c < 4; c++) s[nf][c] *= 0.125f;

        #pragma unroll
        for (int hf = 0; hf < 2; hf++) {
            float mx = -1e30f;
            #pragma unroll
            for (int nf = 0; nf < 8; nf++)
                mx = fmaxf(mx, fmaxf(s[nf][2 * hf], s[nf][2 * hf + 1]));
            mx = fmaxf(mx, __shfl_xor_sync(0xffffffffu, mx, 1));
            mx = fmaxf(mx, __shfl_xor_sync(0xffffffffu, mx, 2));
            float mnew = fmaxf(mrow[hf], mx);
            float alpha = __expf(mrow[hf] - mnew);
            mrow[hf] = mnew;
            float rs = 0.f;
            #pragma unroll
            for (int nf = 0; nf < 8; nf++) {
                float p0 = __expf(s[nf][2 * hf]     - mnew);
                float p1 = __expf(s[nf][2 * hf + 1] - mnew);
                s[nf][2 * hf] = p0; s[nf][2 * hf + 1] = p1;
                rs += p0 + p1;
            }
            rs += __shfl_xor_sync(0xffffffffu, rs, 1);
            rs += __shfl_xor_sync(0xffffffffu, rs, 2);
            lrow[hf] = lrow[hf] * alpha + rs;
            #pragma unroll
            for (int df = 0; df < 8; df++) {
                o[df][2 * hf]     *= alpha;
                o[df][2 * hf + 1] *= alpha;
            }
        }

        uint32_t aP[4][4];
        #pragma unroll
        for (int ks = 0; ks < 4; ks++) {
            f162 h0 = __floats2half2_rn(s[2 * ks][0],     s[2 * ks][1]);
            f162 h1 = __floats2half2_rn(s[2 * ks][2],     s[2 * ks][3]);
            f162 h2 = __floats2half2_rn(s[2 * ks + 1][0], s[2 * ks + 1][1]);
            f162 h3 = __floats2half2_rn(s[2 * ks + 1][2], s[2 * ks + 1][3]);
            aP[ks][0] = *(uint32_t*)&h0; aP[ks][1] = *(uint32_t*)&h1;
            aP[ks][2] = *(uint32_t*)&h2; aP[ks][3] = *(uint32_t*)&h3;
        }

        #pragma unroll
        for (int ks = 0; ks < 4; ks++) {
            #pragma unroll
            for (int gi = 0; gi < 4; gi++) {
                uint32_t t4[4];
                ldsm4t(t4, vB + (ks * 16 * FLDS + gi * 16) * 2);
                mma16816(o[2 * gi],     aP[ks], t4);
                mma16816(o[2 * gi + 1], aP[ks], t4 + 2);
            }
        }
        __syncthreads();
    }

    #pragma unroll
    for (int hf = 0; hf < 2; hf++) {
        float inv = 1.f / lrow[hf];
        size_t r = (size_t)(warp * 16 + (lane >> 2) + hf * 8);
        #pragma unroll
        for (int df = 0; df < 8; df++) {
            int c = df * 8 + (lane & 3) * 2;
            *(f162*)&Oz[r * E_DIM + c] =
                __floats2half2_rn(o[df][2 * hf] * inv, o[df][2 * hf + 1] * inv);
        }
    }
}

// ---------------------------------------------------------------------------
// Fused fp32->fp16 conversion: 7 segments in one launch (grid.y = segment).
// ---------------------------------------------------------------------------
struct CvtSeg { const float* src; f16* dst; size_t n4; };

__global__ void cvt_all(CvtSeg s0, CvtSeg s1, CvtSeg s2, CvtSeg s3,
                        CvtSeg s4, CvtSeg s5, CvtSeg s6)
{
    CvtSeg seg;
    switch (blockIdx.y) {
        case 0: seg = s0; break;
        case 1: seg = s1; break;
        case 2: seg = s2; break;
        case 3: seg = s3; break;
        case 4: seg = s4; break;
        case 5: seg = s5; break;
        default: seg = s6; break;
    }
    size_t i = (size_t)blockIdx.x * blockDim.x + threadIdx.x;
    if (i >= seg.n4) return;
    float4 v = ((const float4*)seg.src)[i];
    ((f162*)seg.dst)[2 * i + 0] = __floats2half2_rn(v.x, v.y);
    ((f162*)seg.dst)[2 * i + 1] = __floats2half2_rn(v.z, v.w);
}

// ---------------------------------------------------------------------------
// LayerNorm (E=1024), fp32 out + optional fp16 out
// ---------------------------------------------------------------------------
__global__ __launch_bounds__(256) void layernorm_rows(
    const float* __restrict__ in,
    const float* __restrict__ g, const float* __restrict__ b,
    float* __restrict__ out, f16* __restrict__ oh)
{
    size_t row = blockIdx.x;
    const float4* x4 = (const float4*)(in + row * E_DIM);
    float4 v = x4[threadIdx.x];

    float s  = v.x + v.y + v.z + v.w;
    float ss = v.x * v.x + v.y * v.y + v.z * v.z + v.w * v.w;
    s  = blockReduceSum256(s);
    ss = blockReduceSum256(ss);

    const float invE = 1.f / (float)E_DIM;
    float mu   = s * invE;
    float var  = ss * invE - mu * mu;
    float rstd = rsqrtf(var + LN_EPS);

    float4 gv = ((const float4*)g)[threadIdx.x];
    float4 bv = ((const float4*)b)[threadIdx.x];
    float4 o;
    o.x = (v.x - mu) * rstd * gv.x + bv.x;
    o.y = (v.y - mu) * rstd * gv.y + bv.y;
    o.z = (v.z - mu) * rstd * gv.z + bv.z;
    o.w = (v.w - mu) * rstd * gv.w + bv.w;
    ((float4*)(out + row * E_DIM))[threadIdx.x] = o;

    if (oh) {
        f162* ph = (f162*)(oh + row * E_DIM);
        ph[2 * threadIdx.x + 0] = __floats2half2_rn(o.x, o.y);
        ph[2 * threadIdx.x + 1] = __floats2half2_rn(o.z, o.w);
    }
}

// ---------------------------------------------------------------------------
// Launch
// Inputs: 0:x 1:Wq 2:Wk 3:Wv 4:Wo 5:g1 6:b1 7:g2 8:b2 9:W1 10:bb1 11:W2 12:bb2
// ---------------------------------------------------------------------------
#define SYMADDR(v, s) cudaGetSymbolAddress((void**)&v, s)
#define GEMM_SMEM(BM, BN) (GSTG * ((BM) + (BN)) * GLDS * 2)
#define FLASH_SMEM ((FT_QT + 4 * FT_KT) * FLDS * 2)   // 55296 B

extern "C" void kernel_launch(void* const* d_in, const int* in_sizes, int n_in,
                              void* d_out, int out_size)
{
    const float* x   = (const float*)d_in[0];
    const float* Wq  = (const float*)d_in[1];
    const float* Wk  = (const float*)d_in[2];
    const float* Wv  = (const float*)d_in[3];
    const float* Wo  = (const float*)d_in[4];
    const float* g1  = (const float*)d_in[5];
    const float* b1  = (const float*)d_in[6];
    const float* g2  = (const float*)d_in[7];
    const float* b2  = (const float*)d_in[8];
    const float* W1  = (const float*)d_in[9];
    const float* bb1 = (const float*)d_in[10];
    const float* W2  = (const float*)d_in[11];
    const float* bb2 = (const float*)d_in[12];
    float* out = (float*)d_out;

    float *res1, *h, *res2;
    f16 *xh, *Wqkvh, *Woh, *W1h, *W2h;
    f16 *qkv, *ah, *hh, *fh;
    SYMADDR(res1, g_res1);
    SYMADDR(h, g_h); SYMADDR(res2, g_res2);
    SYMADDR(xh, g_xh);
    SYMADDR(Wqkvh, g_Wqkvh); SYMADDR(Woh, g_Woh);
    SYMADDR(W1h, g_W1h); SYMADDR(W2h, g_W2h);
    SYMADDR(qkv, g_qkv);
    SYMADDR(ah, g_ah); SYMADDR(hh, g_hh); SYMADDR(fh, g_fh);

    const int SM_128 = GEMM_SMEM(128, 128);   // 110592
    cudaFuncSetAttribute(gemm_fp16<128,128,64,32>,
                         cudaFuncAttributeMaxDynamicSharedMemorySize, SM_128);
    cudaFuncSetAttribute(flash_attn,
                         cudaFuncAttributeMaxDynamicSharedMemorySize, FLASH_SMEM);

    dim3 blk(256);

    // --- single fused convert launch ---
    const size_t nE2 = (size_t)E_DIM * E_DIM;
    CvtSeg s0 = { x,  xh,  (size_t)N_TOK * E_DIM / 4 };
    CvtSeg s1 = { Wq, Wqkvh,            nE2 / 4 };
    CvtSeg s2 = { Wk, Wqkvh + nE2,      nE2 / 4 };
    CvtSeg s3 = { Wv, Wqkvh + 2 * nE2,  nE2 / 4 };
    CvtSeg s4 = { Wo, Woh,              nE2 / 4 };
    CvtSeg s5 = { W1, W1h, (size_t)F_DIM * E_DIM / 4 };
    CvtSeg s6 = { W2, W2h, (size_t)E_DIM * F_DIM / 4 };
    size_t maxN4 = (size_t)N_TOK * E_DIM / 4;
    dim3 gcvt((unsigned)((maxN4 + 255) / 256), 7);
    cvt_all<<<gcvt, blk>>>(s0, s1, s2, s3, s4, s5, s6);

    // --- fused QKV projection -> qkv fp16 [tok, 3072] ---
    dim3 gqkv(QKV_LD / 128, N_TOK / 128, 1);
    gemm_fp16<128,128,64,32><<<gqkv, blk, SM_128>>>(
        xh, E_DIM, 0, 0,  Wqkvh, E_DIM, 0, 0,
        nullptr, qkv, QKV_LD, 0, 0,
        nullptr, nullptr, E_DIM, 1, 1.f, 0);

    // --- fused flash attention -> ah fp16 ---
    flash_attn<<<dim3(S_LEN / FT_QT, BH_NUM), blk, FLASH_SMEM>>>(qkv, ah);

    // --- O projection + residual x ---
    dim3 gp(E_DIM / 128, N_TOK / 128, 1);
    gemm_fp16<128,128,64,32><<<gp, blk, SM_128>>>(
        ah, E_DIM, 0, 0,  Woh, E_DIM, 0, 0,
        res1, nullptr, E_DIM, 0, 0,
        x, nullptr, E_DIM, 1, 1.f, 0);

    // --- LN1 -> h (fp32 + fp16) ---
    layernorm_rows<<<N_TOK, 256>>>(res1, g1, b1, h, hh);

    // --- FFN1: relu(h @ W1^T + bb1) -> fp16 ---
    dim3 gf1(F_DIM / 128, N_TOK / 128, 1);
    gemm_fp16<128,128,64,32><<<gf1, blk, SM_128>>>(
        hh, E_DIM, 0, 0,  W1h, E_DIM, 0, 0,
        nullptr, fh, F_DIM, 0, 0,
        nullptr, bb1, E_DIM, 1, 1.f, 1);

    // --- FFN2: ffn @ W2^T + bb2 + h ---
    gemm_fp16<128,128,64,32><<<gp, blk, SM_128>>>(
        fh, F_DIM, 0, 0,  W2h, F_DIM, 0, 0,
        res2, nullptr, E_DIM, 0, 0,
        h, bb2, F_DIM, 1, 1.f, 0);

    // --- LN2 -> out ---
    layernorm_rows<<<N_TOK, 256>>>(res2, g2, b2, out, nullptr);
}